// round 5
// baseline (speedup 1.0000x reference)
#include <cuda_runtime.h>

// Fused 2-layer LSTM + FC decoder — pair-split f32x2 edition.
// x:[4096,256,16] -> LSTM(16->64) -> LSTM(64->1) -> FC(1->1) -> out:[4096,256,1]
//
// block = NB(4) batch elements, 512 threads, grid 1024, 2 blocks/SM (50% occ).
// Thread pair (2g, 2g+1) owns gate g: each half holds 32 h-weights + 8 x-weights
// in registers (packed f32x2), computes a half-dot with fma.rn.f32x2, pair
// combines via shfl_xor(1). Even thread applies activation + stores gact.
// 2 __syncthreads/step; x double-buffered through registers (threads 448-511).
// Layer 2 (H=1) + FC deferred one step on warps 0-3, overlapped with gates.

#define T_STEPS 256
#define IN_DIM  16
#define H1      64
#define G1      256   // 4*H1
#define NB      4
#define THREADS 512

typedef unsigned long long ull;

__device__ __forceinline__ ull fma2(ull a, ull b, ull c) {
    ull d;
    asm("fma.rn.f32x2 %0, %1, %2, %3;" : "=l"(d) : "l"(a), "l"(b), "l"(c));
    return d;
}
__device__ __forceinline__ float2 u2f(ull v) {
    float2 r;
    asm("mov.b64 {%0, %1}, %2;" : "=f"(r.x), "=f"(r.y) : "l"(v));
    return r;
}

__device__ __forceinline__ float sigmoid_f(float x) {
    return __fdividef(1.0f, 1.0f + __expf(-x));
}
__device__ __forceinline__ float tanh_f(float x) {
    return __fdividef(2.0f, 1.0f + __expf(-2.0f * x)) - 1.0f;
}

// One LSTM2 (H=1) step + FC for one batch element, done by one warp.
// w_ih2 row read via LDG (L1-hit) each step to keep register pressure low.
__device__ __forceinline__ void layer2_step(const float* __restrict__ hb,
                                            const float* __restrict__ w2p,
                                            float bias2, float whh2,
                                            float fcw, float fcb,
                                            float& h2, float& c2,
                                            float* __restrict__ outp, int lane)
{
    float part = 0.0f;
    #pragma unroll
    for (int m = 0; m < 8; m++) part = fmaf(w2p[m], hb[m], part);
    part += __shfl_down_sync(0xffffffffu, part, 4);
    part += __shfl_down_sync(0xffffffffu, part, 2);
    part += __shfl_down_sync(0xffffffffu, part, 1);
    float gate = fmaf(whh2, h2, part + bias2);   // valid where (lane&7)==0
    float gi = __shfl_sync(0xffffffffu, gate, 0);
    float gf = __shfl_sync(0xffffffffu, gate, 8);
    float gg = __shfl_sync(0xffffffffu, gate, 16);
    float go = __shfl_sync(0xffffffffu, gate, 24);
    float ii = sigmoid_f(gi);
    float ff = sigmoid_f(gf);
    float g2 = tanh_f(gg);
    float oo = sigmoid_f(go);
    c2 = fmaf(ff, c2, ii * g2);
    h2 = oo * tanh_f(c2);
    if (lane == 0) *outp = fmaf(h2, fcw, fcb);
}

__global__ __launch_bounds__(THREADS, 2)
void lstm_fused_kernel(const float* __restrict__ x,
                       const float* __restrict__ w_ih1, const float* __restrict__ w_hh1,
                       const float* __restrict__ b_ih1, const float* __restrict__ b_hh1,
                       const float* __restrict__ w_ih2, const float* __restrict__ w_hh2,
                       const float* __restrict__ b_ih2, const float* __restrict__ b_hh2,
                       const float* __restrict__ fc_w, const float* __restrict__ fc_b,
                       float* __restrict__ out)
{
    __shared__ __align__(16) float x_sh[NB * IN_DIM];   // staged x for current step
    __shared__ __align__(16) float h_sh[NB * H1];       // layer-1 hidden state
    __shared__ float gact[NB * G1];                      // activated gates

    const int tid  = threadIdx.x;
    const int b0   = blockIdx.x * NB;
    const int wid  = tid >> 5;
    const int lane = tid & 31;
    const int g    = tid >> 1;    // gate id 0..255
    const int half = tid & 1;     // which half of the dot product

    // ---- layer-1 half-weights in registers as packed f32x2 ----
    ull whh[16];   // 32 floats: w_hh1[g, half*32 .. half*32+32)
    ull wih[4];    // 8 floats:  w_ih1[g, half*8 .. half*8+8)
    {
        const ulonglong2* wr = (const ulonglong2*)(w_hh1 + g * H1 + half * 32);
        #pragma unroll
        for (int m = 0; m < 8; m++) { ulonglong2 v = wr[m]; whh[2*m] = v.x; whh[2*m+1] = v.y; }
        const ulonglong2* wi = (const ulonglong2*)(w_ih1 + g * IN_DIM + half * 8);
        #pragma unroll
        for (int m = 0; m < 2; m++) { ulonglong2 v = wi[m]; wih[2*m] = v.x; wih[2*m+1] = v.y; }
    }
    const float bias1 = b_ih1[g] + b_hh1[g];   // same for both halves

    // ---- layer-2 + FC per-warp setup (only warps 0..NB-1 use it) ----
    const int q  = lane >> 3;
    const int ch = lane & 7;
    const float* w2p  = w_ih2 + q * H1 + ch * 8;   // LDG per step (L1-hit)
    const float bias2 = b_ih2[q] + b_hh2[q];
    const float whh2  = w_hh2[q];
    const float fcw   = fc_w[0];
    const float fcb   = fc_b[0];

    // ---- states ----
    float c1 = 0.0f;            // only meaningful on even threads
    float c2 = 0.0f, h2 = 0.0f; // layer-2 (warps 0-3, warp-uniform)
    if (tid < NB * H1) h_sh[tid] = 0.0f;

    const int cls    = g >> 6;        // 0:i 1:f 2:g 3:o
    const int upd_nb = g >> 6;        // even threads: update owner (nb, j)
    const int upd_j  = g & 63;
    const float* hb2 = h_sh + wid * H1 + ch * 8;
    float* outb = out + (b0 + wid) * T_STEPS;

    // x staging: threads 448..511 own (nb = idx>>4, i = idx&15)
    const bool xduty = (tid >= 448);
    const int  xidx  = tid - 448;
    const int  xnb   = (xidx >> 4) & 3;
    const int  xi    = tid & 15;
    const float* xsrc = x + ((b0 + xnb) * T_STEPS) * IN_DIM + xi;

    if (xduty) x_sh[xidx] = xsrc[0];
    __syncthreads();

    for (int t = 0; t < T_STEPS; t++) {
        // ---- phase 1: prefetch x(t+1); half-gates(t); layer2(t-1) ----
        float xr = 0.0f;
        if (xduty && t + 1 < T_STEPS) xr = xsrc[(t + 1) * IN_DIM];

        #pragma unroll
        for (int nb = 0; nb < NB; nb++) {
            ull a0 = 0, a1 = 0;
            const ulonglong2* hv = (const ulonglong2*)(h_sh + nb * H1 + half * 32);
            #pragma unroll
            for (int m = 0; m < 8; m += 2) {
                ulonglong2 p = hv[m];
                ulonglong2 r = hv[m + 1];
                a0 = fma2(whh[2*m + 0], p.x, a0);
                a1 = fma2(whh[2*m + 1], p.y, a1);
                a0 = fma2(whh[2*m + 2], r.x, a0);
                a1 = fma2(whh[2*m + 3], r.y, a1);
            }
            {
                const ulonglong2* xv = (const ulonglong2*)(x_sh + nb * IN_DIM + half * 8);
                ulonglong2 p = xv[0];
                ulonglong2 r = xv[1];
                a0 = fma2(wih[0], p.x, a0);
                a1 = fma2(wih[1], p.y, a1);
                a0 = fma2(wih[2], r.x, a0);
                a1 = fma2(wih[3], r.y, a1);
            }
            float2 f0 = u2f(a0), f1 = u2f(a1);
            float s = (f0.x + f0.y) + (f1.x + f1.y);
            s += __shfl_xor_sync(0xffffffffu, s, 1);   // combine halves
            float pre = s + bias1;
            float act = (cls == 2) ? tanh_f(pre) : sigmoid_f(pre);
            if (half == 0) gact[nb * G1 + g] = act;
        }

        // deferred layer-2 for t-1 (pure reader of h_sh = h1(t-1))
        if (wid < NB && t > 0) {
            layer2_step(hb2, w2p, bias2, whh2, fcw, fcb, h2, c2, outb + (t - 1), lane);
        }
        __syncthreads();

        // ---- phase 2: cell/hidden update (even threads); publish x(t+1) ----
        if (half == 0) {
            const float* gb = gact + upd_nb * G1;
            float gi = gb[upd_j];
            float gf = gb[H1 + upd_j];
            float gg = gb[2 * H1 + upd_j];
            float go = gb[3 * H1 + upd_j];
            c1 = fmaf(gf, c1, gi * gg);
            h_sh[upd_nb * H1 + upd_j] = go * tanh_f(c1);
        }
        if (xduty) x_sh[xidx] = xr;
        __syncthreads();   // h(t), x(t+1) published
    }

    // Tail: layer-2 + FC for the final timestep (h1(T-1))
    if (wid < NB) {
        layer2_step(hb2, w2p, bias2, whh2, fcw, fcb, h2, c2, outb + (T_STEPS - 1), lane);
    }
}

extern "C" void kernel_launch(void* const* d_in, const int* in_sizes, int n_in,
                              void* d_out, int out_size) {
    const int B = in_sizes[0] / (T_STEPS * IN_DIM);   // 4096
    lstm_fused_kernel<<<B / NB, THREADS>>>(
        (const float*)d_in[0],
        (const float*)d_in[1], (const float*)d_in[2],
        (const float*)d_in[3], (const float*)d_in[4],
        (const float*)d_in[5], (const float*)d_in[6],
        (const float*)d_in[7], (const float*)d_in[8],
        (const float*)d_in[9], (const float*)d_in[10],
        (float*)d_out);
}

// round 8
// speedup vs baseline: 2.0940x; 2.0940x over previous
#include <cuda_runtime.h>

// Fused 2-layer LSTM + FC decoder — NB=16 amortized edition (x-dot fixed).
// x:[4096,256,16] -> LSTM(16->64) -> LSTM(64->1) -> FC(1->1) -> out:[4096,256,1]
//
// block = NB(16) batch elements, 256 threads, grid 256 (~1 wave, 2 blocks/SM).
// Thread g owns gate g of layer 1; weight row in registers (packed f32x2);
// per step: 16 independent 80-MAC dots via fma.rn.f32x2. 2 syncthreads/step.
// x double-buffered through registers (1 float/thread). Layer 2 (H=1)+FC
// deferred one step, 2 batches per warp on warps 0-7, overlapped with gates.

#define T_STEPS 256
#define IN_DIM  16
#define H1      64
#define G1      256   // 4*H1
#define NB      16
#define THREADS 256

typedef unsigned long long ull;

__device__ __forceinline__ ull fma2(ull a, ull b, ull c) {
    ull d;
    asm("fma.rn.f32x2 %0, %1, %2, %3;" : "=l"(d) : "l"(a), "l"(b), "l"(c));
    return d;
}
__device__ __forceinline__ float2 u2f(ull v) {
    float2 r;
    asm("mov.b64 {%0, %1}, %2;" : "=f"(r.x), "=f"(r.y) : "l"(v));
    return r;
}

__device__ __forceinline__ float sigmoid_f(float x) {
    return __fdividef(1.0f, 1.0f + __expf(-x));
}
__device__ __forceinline__ float tanh_f(float x) {
    return __fdividef(2.0f, 1.0f + __expf(-2.0f * x)) - 1.0f;
}

// One LSTM2 (H=1) step + FC for one batch element, done by one warp.
__device__ __forceinline__ void layer2_step(const float* __restrict__ hb,
                                            const float w2[8], float bias2, float whh2,
                                            float fcw, float fcb,
                                            float& h2, float& c2,
                                            float* __restrict__ outp, int lane)
{
    float part = 0.0f;
    #pragma unroll
    for (int m = 0; m < 8; m++) part = fmaf(w2[m], hb[m], part);
    part += __shfl_down_sync(0xffffffffu, part, 4);
    part += __shfl_down_sync(0xffffffffu, part, 2);
    part += __shfl_down_sync(0xffffffffu, part, 1);
    float gate = fmaf(whh2, h2, part + bias2);   // valid where (lane&7)==0
    float gi = __shfl_sync(0xffffffffu, gate, 0);
    float gf = __shfl_sync(0xffffffffu, gate, 8);
    float gg = __shfl_sync(0xffffffffu, gate, 16);
    float go = __shfl_sync(0xffffffffu, gate, 24);
    float ii = sigmoid_f(gi);
    float ff = sigmoid_f(gf);
    float g2 = tanh_f(gg);
    float oo = sigmoid_f(go);
    c2 = fmaf(ff, c2, ii * g2);
    h2 = oo * tanh_f(c2);
    if (lane == 0) *outp = fmaf(h2, fcw, fcb);
}

__global__ __launch_bounds__(THREADS, 2)
void lstm_fused_kernel(const float* __restrict__ x,
                       const float* __restrict__ w_ih1, const float* __restrict__ w_hh1,
                       const float* __restrict__ b_ih1, const float* __restrict__ b_hh1,
                       const float* __restrict__ w_ih2, const float* __restrict__ w_hh2,
                       const float* __restrict__ b_ih2, const float* __restrict__ b_hh2,
                       const float* __restrict__ fc_w, const float* __restrict__ fc_b,
                       float* __restrict__ out)
{
    __shared__ __align__(16) float x_sh[NB * IN_DIM];   // 256: staged x(t)
    __shared__ __align__(16) float h_sh[NB * H1];       // 1024: layer-1 hidden
    __shared__ float gact[NB * G1];                      // 4096: activated gates

    const int tid  = threadIdx.x;
    const int b0   = blockIdx.x * NB;
    const int wid  = tid >> 5;
    const int lane = tid & 31;

    // ---- layer-1 weights in registers as packed f32x2 (thread = gate tid) ----
    ull whh[32];   // 64 floats
    ull wih[8];    // 16 floats
    {
        const ulonglong2* wr = (const ulonglong2*)(w_hh1 + tid * H1);
        #pragma unroll
        for (int m = 0; m < 16; m++) { ulonglong2 v = wr[m]; whh[2*m] = v.x; whh[2*m+1] = v.y; }
        const ulonglong2* wi = (const ulonglong2*)(w_ih1 + tid * IN_DIM);
        #pragma unroll
        for (int m = 0; m < 4; m++) { ulonglong2 v = wi[m]; wih[2*m] = v.x; wih[2*m+1] = v.y; }
    }
    const float bias1 = b_ih1[tid] + b_hh1[tid];

    // ---- layer-2 + FC per-warp setup: warp w -> batches 2w, 2w+1 ----
    const int q  = lane >> 3;
    const int ch = lane & 7;
    float w2[8];
    #pragma unroll
    for (int m = 0; m < 8; m++) w2[m] = w_ih2[q * H1 + ch * 8 + m];
    const float bias2 = b_ih2[q] + b_hh2[q];
    const float whh2  = w_hh2[q];
    const float fcw   = fc_w[0];
    const float fcb   = fc_b[0];

    // ---- states ----
    float c1[4];                 // 4 cells per thread: cell id = k*256 + tid
    #pragma unroll
    for (int k = 0; k < 4; k++) c1[k] = 0.0f;
    float c2[2] = {0.0f, 0.0f};  // layer-2 per-warp (2 batches)
    float h2[2] = {0.0f, 0.0f};
    #pragma unroll
    for (int k = 0; k < 4; k++) h_sh[k * 256 + tid] = 0.0f;

    const int cls = tid >> 6;    // 0:i 1:f 2:g 3:o
    const float* hb2a = h_sh + (wid * 2 + 0) * H1 + ch * 8;
    const float* hb2b = h_sh + (wid * 2 + 1) * H1 + ch * 8;
    float* outa = out + (b0 + wid * 2 + 0) * T_STEPS;
    float* outc = out + (b0 + wid * 2 + 1) * T_STEPS;

    // x staging: every thread owns (xnb = tid>>4, xi = tid&15)
    const float* xsrc = x + ((b0 + (tid >> 4)) * T_STEPS) * IN_DIM + (tid & 15);
    x_sh[tid] = xsrc[0];
    __syncthreads();

    for (int t = 0; t < T_STEPS; t++) {
        // ---- phase 1: prefetch x(t+1); gates(t) for 16 batches; layer2(t-1) ----
        float xr = 0.0f;
        if (t + 1 < T_STEPS) xr = xsrc[(t + 1) * IN_DIM];

        #pragma unroll 4
        for (int nb = 0; nb < NB; nb++) {
            ull a0 = 0, a1 = 0, a2 = 0, a3 = 0;
            const ulonglong2* hv = (const ulonglong2*)(h_sh + nb * H1);
            #pragma unroll
            for (int m = 0; m < 16; m += 2) {
                ulonglong2 p = hv[m];
                ulonglong2 r = hv[m + 1];
                a0 = fma2(whh[2*m + 0], p.x, a0);
                a1 = fma2(whh[2*m + 1], p.y, a1);
                a2 = fma2(whh[2*m + 2], r.x, a2);
                a3 = fma2(whh[2*m + 3], r.y, a3);
            }
            // full 16-float x projection (4 ulonglong2 loads, wih[0..7])
            const ulonglong2* xv = (const ulonglong2*)(x_sh + nb * IN_DIM);
            #pragma unroll
            for (int m = 0; m < 4; m += 2) {
                ulonglong2 p = xv[m];
                ulonglong2 r = xv[m + 1];
                a0 = fma2(wih[2*m + 0], p.x, a0);
                a1 = fma2(wih[2*m + 1], p.y, a1);
                a2 = fma2(wih[2*m + 2], r.x, a2);
                a3 = fma2(wih[2*m + 3], r.y, a3);
            }
            float2 f0 = u2f(a0), f1 = u2f(a1), f2 = u2f(a2), f3 = u2f(a3);
            float pre = ((f0.x + f0.y) + (f1.x + f1.y))
                      + ((f2.x + f2.y) + (f3.x + f3.y)) + bias1;
            gact[nb * G1 + tid] = (cls == 2) ? tanh_f(pre) : sigmoid_f(pre);
        }

        // deferred layer-2 for t-1 (pure reader of h_sh = h1(t-1)); 2 batches/warp
        if (t > 0) {
            layer2_step(hb2a, w2, bias2, whh2, fcw, fcb, h2[0], c2[0], outa + (t - 1), lane);
            layer2_step(hb2b, w2, bias2, whh2, fcw, fcb, h2[1], c2[1], outc + (t - 1), lane);
        }
        __syncthreads();

        // ---- phase 2: update 4 cells per thread; publish x(t+1) ----
        #pragma unroll
        for (int k = 0; k < 4; k++) {
            const int cell = k * 256 + tid;          // 0..1023
            const int unb  = cell >> 6;              // batch 0..15
            const int uj   = cell & 63;              // hidden index
            const float* gb = gact + unb * G1;
            float gi = gb[uj];
            float gf = gb[H1 + uj];
            float gg = gb[2 * H1 + uj];
            float go = gb[3 * H1 + uj];
            c1[k] = fmaf(gf, c1[k], gi * gg);
            h_sh[unb * H1 + uj] = go * tanh_f(c1[k]);
        }
        x_sh[tid] = xr;
        __syncthreads();   // h(t), x(t+1) published
    }

    // Tail: layer-2 + FC for the final timestep (h1(T-1))
    layer2_step(hb2a, w2, bias2, whh2, fcw, fcb, h2[0], c2[0], outa + (T_STEPS - 1), lane);
    layer2_step(hb2b, w2, bias2, whh2, fcw, fcb, h2[1], c2[1], outc + (T_STEPS - 1), lane);
}

extern "C" void kernel_launch(void* const* d_in, const int* in_sizes, int n_in,
                              void* d_out, int out_size) {
    const int B = in_sizes[0] / (T_STEPS * IN_DIM);   // 4096
    lstm_fused_kernel<<<B / NB, THREADS>>>(
        (const float*)d_in[0],
        (const float*)d_in[1], (const float*)d_in[2],
        (const float*)d_in[3], (const float*)d_in[4],
        (const float*)d_in[5], (const float*)d_in[6],
        (const float*)d_in[7], (const float*)d_in[8],
        (const float*)d_in[9], (const float*)d_in[10],
        (float*)d_out);
}